// round 8
// baseline (speedup 1.0000x reference)
#include <cuda_runtime.h>
#include <math.h>

typedef unsigned long long u64;

// ---- packed f32x2 helpers (sm_100+ PTX) ------------------------------------
__device__ __forceinline__ u64 pack2(float lo, float hi) {
    u64 r;
    asm("mov.b64 %0, {%1, %2};" : "=l"(r) : "f"(lo), "f"(hi));
    return r;
}
__device__ __forceinline__ void fma2(u64 &d, u64 a, u64 b) {
    asm("fma.rn.f32x2 %0, %1, %2, %0;" : "+l"(d) : "l"(a), "l"(b));
}
__device__ __forceinline__ float2 unpack2(u64 v) {
    float lo, hi;
    asm("mov.b64 {%0, %1}, %2;" : "=f"(lo), "=f"(hi) : "l"(v));
    return make_float2(lo, hi);
}

static constexpr int IN_DIM  = 592;
static constexpr int W_NUMEL = 21760;
static constexpr int NT      = 256;   // threads per CTA

// ---- one irrep block: out[z, w*DIM+i] = pw * sum_u W[u,w] * x[z, u*DIM+i] --
// CTA handles ZT batch rows. Register tile: TR rows of the flattened (z,i)
// dimension x TW weight columns per thread (TW even, accumulate as f32x2).
template<int MUL, int DIM, int XOFF, int WOFF, int ZT, int TR, int TW>
__global__ __launch_bounds__(NT)
void irrep_linear_kernel(const float* __restrict__ x,
                         const float* __restrict__ wts,
                         float* __restrict__ out,
                         int batch, float pw)
{
    constexpr int RL  = MUL * DIM;      // slice length per row
    constexpr int LDP = RL + 4;         // padded smem row (keeps float4 align, breaks bank repeat)
    constexpr int TW2 = TW / 2;
    constexpr int NWT = MUL / TW;       // thread groups along w
    constexpr int NRT = (ZT * DIM) / TR;// thread groups along r=(z,i)
    constexpr int ZPT = TR / DIM;       // z rows per thread tile
    constexpr int RL4 = RL / 4;
    static_assert(NWT * NRT == NT, "thread mapping must cover CTA");
    static_assert(TR % DIM == 0, "row tile must be whole z rows");
    static_assert((TW & 1) == 0, "f32x2 needs even TW");

    extern __shared__ float smem[];
    float* Ws = smem;                   // [MUL*MUL], pw folded in
    float* Xs = smem + MUL * MUL;       // [ZT][LDP]

    const int tid = threadIdx.x;
    const int z0  = blockIdx.x * ZT;
    const int zc  = min(ZT, batch - z0);

    // Stage weights with pw folded in (w is tiny; stays hot in L2)
    for (int idx = tid; idx < MUL * MUL; idx += NT)
        Ws[idx] = pw * wts[WOFF + idx];

    // Stage x tile, coalesced float4
    for (int idx = tid; idx < zc * RL4; idx += NT) {
        int z = idx / RL4;
        int c = idx - z * RL4;
        *(float4*)&Xs[z * LDP + 4 * c] =
            *(const float4*)&x[(size_t)(z0 + z) * IN_DIM + XOFF + 4 * c];
    }
    if (zc < ZT) {  // tail CTA only: keep garbage out of the math
        for (int idx = tid; idx < (ZT - zc) * LDP; idx += NT)
            Xs[zc * LDP + idx] = 0.f;
    }
    __syncthreads();

    const int wt = tid % NWT;
    const int rt = tid / NWT;
    const int w0 = wt * TW;
    const int r0 = rt * TR;
    const int zb = r0 / DIM;

    u64 acc[TR][TW2];
    #pragma unroll
    for (int k = 0; k < TR; ++k)
        #pragma unroll
        for (int j = 0; j < TW2; ++j)
            acc[k][j] = 0ull;

    const float* xrow = &Xs[zb * LDP];
    const float* wcol = &Ws[w0];

    #pragma unroll 4
    for (int u = 0; u < MUL; ++u) {
        u64 wv[TW2];
        #pragma unroll
        for (int j = 0; j < TW2; ++j)
            wv[j] = *(const u64*)(wcol + u * MUL + 2 * j);
        #pragma unroll
        for (int zz = 0; zz < ZPT; ++zz) {
            #pragma unroll
            for (int i = 0; i < DIM; ++i) {
                float a  = xrow[zz * LDP + u * DIM + i];
                u64   ap = pack2(a, a);
                #pragma unroll
                for (int j = 0; j < TW2; ++j)
                    fma2(acc[zz * DIM + i][j], wv[j], ap);
            }
        }
    }
    __syncthreads();  // all reads of Xs done; reuse it as output staging

    // Scatter accumulators into smem (output slice has identical shape)
    #pragma unroll
    for (int k = 0; k < TR; ++k) {
        const int zz = k / DIM;
        const int i  = k % DIM;
        float* orow = &Xs[(zb + zz) * LDP + i];
        #pragma unroll
        for (int j = 0; j < TW2; ++j) {
            float2 v = unpack2(acc[k][j]);
            orow[(w0 + 2 * j    ) * DIM] = v.x;
            orow[(w0 + 2 * j + 1) * DIM] = v.y;
        }
    }
    __syncthreads();

    // Coalesced float4 store to global
    for (int idx = tid; idx < zc * RL4; idx += NT) {
        int z = idx / RL4;
        int c = idx - z * RL4;
        *(float4*)&out[(size_t)(z0 + z) * IN_DIM + XOFF + 4 * c] =
            *(const float4*)&Xs[z * LDP + 4 * c];
    }
}

// ---- launcher ---------------------------------------------------------------
template<int MUL, int DIM, int XOFF, int WOFF, int ZT, int TR, int TW>
static void launch_block(const float* x, const float* w, float* out, int batch)
{
    constexpr int LDP = MUL * DIM + 4;
    const size_t sm = (size_t)(MUL * MUL + ZT * LDP) * sizeof(float);
    auto kfn = irrep_linear_kernel<MUL, DIM, XOFF, WOFF, ZT, TR, TW>;
    cudaFuncSetAttribute(kfn, cudaFuncAttributeMaxDynamicSharedMemorySize, (int)sm);
    const int grid = (batch + ZT - 1) / ZT;
    const float pw = (float)(1.0 / sqrt((double)MUL));
    kfn<<<grid, NT, sm>>>(x, w, out, batch, pw);
}

extern "C" void kernel_launch(void* const* d_in, const int* in_sizes, int n_in,
                              void* d_out, int out_size)
{
    const float* x = (const float*)d_in[0];
    const float* w = (const float*)d_in[1];
    int xsz = in_sizes[0];
    if (n_in >= 2 && in_sizes[0] == W_NUMEL) {   // robust to input ordering
        x = (const float*)d_in[1];
        w = (const float*)d_in[0];
        xsz = in_sizes[1];
    }
    float* out = (float*)d_out;
    const int batch = xsz / IN_DIM;

    //                 MUL DIM XOFF WOFF   ZT  TR  TW
    launch_block<128, 1,   0,     0, 64,  4,  8>(x, w, out, batch);
    launch_block< 64, 3, 128, 16384, 64,  6,  8>(x, w, out, batch);
    launch_block< 32, 5, 320, 20480, 64, 10,  4>(x, w, out, batch);
    launch_block< 16, 7, 480, 21504, 64, 14,  2>(x, w, out, batch);
}

// round 9
// speedup vs baseline: 1.0248x; 1.0248x over previous
#include <cuda_runtime.h>
#include <math.h>

typedef unsigned long long u64;

// ---- packed f32x2 helpers (sm_100+) ----------------------------------------
__device__ __forceinline__ u64 pack2(float lo, float hi) {
    u64 r;
    asm("mov.b64 %0, {%1, %2};" : "=l"(r) : "f"(lo), "f"(hi));
    return r;
}
__device__ __forceinline__ void fma2(u64 &d, u64 a, u64 b) {
    asm("fma.rn.f32x2 %0, %1, %2, %0;" : "+l"(d) : "l"(a), "l"(b));
}
__device__ __forceinline__ float2 unpack2(u64 v) {
    float lo, hi;
    asm("mov.b64 {%0, %1}, %2;" : "=f"(lo), "=f"(hi) : "l"(v));
    return make_float2(lo, hi);
}

static constexpr int IN_DIM  = 592;
static constexpr int W_NUMEL = 21760;
static constexpr int NT      = 256;

// out[z, w*DIM+i] = pw * sum_u W[u,w] * x[z, u*DIM+i]
//
// x slice staged in smem as DUPLICATED u64 pairs (v,v) with pw folded in →
// the broadcast operand of fma.rn.f32x2 is a single LDS.64, zero MOVs.
// Weights read straight from global as natural (w, w+1) u64 pairs via __ldg
// (L1-resident across CTAs, no per-CTA staging traffic, no bank conflicts).
// Thread tile: TR rows of r=(z,i) x TW weight columns, columns strided by NWT
// pairs so each warp-wide LDG.64 is one contiguous cache line.
template<int MUL, int DIM, int XOFF, int WOFF, int ZT, int TR, int TW>
__global__ __launch_bounds__(NT)
void irrep_kernel(const float* __restrict__ x,
                  const float* __restrict__ wts,
                  float* __restrict__ out,
                  int batch, float pw)
{
    constexpr int RL  = MUL * DIM;
    constexpr int RLP = RL + 2;        // u64 row stride: row delta = 4 banks mod 32
    constexpr int TW2 = TW / 2;
    constexpr int NWT = MUL / TW;      // thread groups along w (strided mapping)
    constexpr int NRT = NT / NWT;      // thread groups along r
    constexpr int RL4 = RL / 4;
    constexpr int LDO = RL + 4;        // float row stride for output staging
    static_assert(NRT * TR == ZT * DIM, "tile covers CTA rows");
    static_assert(TR % DIM == 0, "whole z rows per thread");
    static_assert((TW & 1) == 0, "f32x2 needs even TW");

    extern __shared__ u64 smem[];
    u64* Xd = smem;                    // [ZT][RLP] duplicated pairs, pw folded

    const int tid = threadIdx.x;
    const int z0  = blockIdx.x * ZT;
    const int zc  = min(ZT, batch - z0);

    // Stage x: coalesced float4 reads, duplicated u64 writes, pw folded in.
    for (int idx = tid; idx < zc * RL4; idx += NT) {
        int z = idx / RL4, c = idx - z * RL4;
        float4 v = *(const float4*)&x[(size_t)(z0 + z) * IN_DIM + XOFF + 4 * c];
        u64* p = &Xd[z * RLP + 4 * c];
        float a = v.x * pw, b = v.y * pw, cc = v.z * pw, d = v.w * pw;
        p[0] = pack2(a, a);
        p[1] = pack2(b, b);
        p[2] = pack2(cc, cc);
        p[3] = pack2(d, d);
    }
    if (zc < ZT) {
        for (int idx = tid; idx < (ZT - zc) * RLP; idx += NT)
            Xd[zc * RLP + idx] = 0ull;
    }
    __syncthreads();

    const int wt = tid % NWT;
    const int rt = tid / NWT;
    const int zb = (rt * TR) / DIM;

    const u64* __restrict__ Wg =
        reinterpret_cast<const u64*>(wts + WOFF) + wt;   // u64 = (W[u,2p], W[u,2p+1])
    const u64* Xr = &Xd[zb * RLP];

    u64 acc[TR][TW2];
    #pragma unroll
    for (int k = 0; k < TR; ++k)
        #pragma unroll
        for (int j = 0; j < TW2; ++j)
            acc[k][j] = 0ull;

    #pragma unroll 4
    for (int u = 0; u < MUL; ++u) {
        u64 wp[TW2];
        #pragma unroll
        for (int j = 0; j < TW2; ++j)
            wp[j] = __ldg(Wg + (size_t)u * (MUL / 2) + j * NWT);
        u64 xv[TR];
        #pragma unroll
        for (int k = 0; k < TR; ++k) {
            const int zz = k / DIM, i = k % DIM;
            xv[k] = Xr[zz * RLP + u * DIM + i];
        }
        #pragma unroll
        for (int k = 0; k < TR; ++k)
            #pragma unroll
            for (int j = 0; j < TW2; ++j)
                fma2(acc[k][j], xv[k], wp[j]);
    }
    __syncthreads();   // all Xd reads done; reuse buffer as output staging

    // Scatter accumulators into smem (irrep-layout), then coalesced store.
    float* Os = reinterpret_cast<float*>(smem);
    #pragma unroll
    for (int k = 0; k < TR; ++k) {
        const int zz = k / DIM, i = k % DIM;
        float* orow = &Os[(zb + zz) * LDO + i];
        #pragma unroll
        for (int j = 0; j < TW2; ++j) {
            float2 v = unpack2(acc[k][j]);
            const int w0 = 2 * (wt + j * NWT);
            orow[(w0    ) * DIM] = v.x;
            orow[(w0 + 1) * DIM] = v.y;
        }
    }
    __syncthreads();

    for (int idx = tid; idx < zc * RL4; idx += NT) {
        int z = idx / RL4, c = idx - z * RL4;
        *(float4*)&out[(size_t)(z0 + z) * IN_DIM + XOFF + 4 * c] =
            *(const float4*)&Os[z * LDO + 4 * c];
    }
}

// ---- launcher ---------------------------------------------------------------
template<int MUL, int DIM, int XOFF, int WOFF, int ZT, int TR, int TW>
static void launch_block(const float* x, const float* w, float* out, int batch)
{
    constexpr int RLP = MUL * DIM + 2;
    const size_t sm = (size_t)ZT * RLP * sizeof(u64);
    auto kfn = irrep_kernel<MUL, DIM, XOFF, WOFF, ZT, TR, TW>;
    cudaFuncSetAttribute(kfn, cudaFuncAttributeMaxDynamicSharedMemorySize, (int)sm);
    const int grid = (batch + ZT - 1) / ZT;
    const float pw = (float)(1.0 / sqrt((double)MUL));
    kfn<<<grid, NT, sm>>>(x, w, out, batch, pw);
}

extern "C" void kernel_launch(void* const* d_in, const int* in_sizes, int n_in,
                              void* d_out, int out_size)
{
    const float* x = (const float*)d_in[0];
    const float* w = (const float*)d_in[1];
    int xsz = in_sizes[0];
    if (n_in >= 2 && in_sizes[0] == W_NUMEL) {   // robust to input ordering
        x = (const float*)d_in[1];
        w = (const float*)d_in[0];
        xsz = in_sizes[1];
    }
    float* out = (float*)d_out;
    const int batch = xsz / IN_DIM;

    //                 MUL DIM XOFF  WOFF  ZT  TR  TW
    launch_block<128, 1,   0,     0, 64,  4,  8>(x, w, out, batch);  // 66.6 KB smem
    launch_block< 64, 3, 128, 16384, 32,  3,  8>(x, w, out, batch);  // 49.7 KB
    launch_block< 32, 5, 320, 20480, 32,  5,  4>(x, w, out, batch);  // 41.5 KB
    launch_block< 16, 7, 480, 21504, 64,  7,  4>(x, w, out, batch);  // 58.4 KB
}